// round 3
// baseline (speedup 1.0000x reference)
#include <cuda_runtime.h>
#include <math.h>
#include <stdint.h>

// Problem constants (fixed by the reference setup_inputs()).
#define NN 8192
#define DD 512
#define INV_T 10.0f

// -------- scratch (allocation-free: __device__ globals) --------
__device__ float g_fn[(size_t)NN * DD];           // normalized features, 16 MB
__device__ float g_S[(size_t)NN * NN];            // similarity logits, 256 MB
__device__ float g_rowval[NN];                    // per-anchor loss contribution
__device__ int   g_rowflag[NN];                   // processed && has_pos

// ---------------------------------------------------------------
// Kernel 1: row-normalize. One warp per row (512 floats -> 16/lane).
// ---------------------------------------------------------------
__global__ void normalize_kernel(const float* __restrict__ feats, int N) {
    int row  = blockIdx.x * (blockDim.x >> 5) + (threadIdx.x >> 5);
    int lane = threadIdx.x & 31;
    if (row >= N) return;
    const float* src = feats + (size_t)row * DD;
    float v[16];
    float ss = 0.f;
#pragma unroll
    for (int i = 0; i < 16; i++) {
        v[i] = src[lane + i * 32];
        ss += v[i] * v[i];
    }
#pragma unroll
    for (int o = 16; o > 0; o >>= 1)
        ss += __shfl_xor_sync(0xffffffffu, ss, o);
    float inv = 1.0f / sqrtf(ss);
    float* dst = g_fn + (size_t)row * DD;
#pragma unroll
    for (int i = 0; i < 16; i++)
        dst[lane + i * 32] = v[i] * inv;
}

// ---------------------------------------------------------------
// Kernel 2: S = (fn @ fn^T) * INV_T.  Classic tiled fp32 SGEMM.
// BM=BN=128, BK=16, 256 threads, 8x8 per-thread micro-tile.
// Both operands are rows of g_fn (A row-major, B = A^T logically).
// ---------------------------------------------------------------
#define BM 128
#define BN 128
#define BK 16
#define TM 8
#define TN 8

__global__ __launch_bounds__(256, 2)
void gemm_kernel(int N) {
    __shared__ float As[BK][BM];
    __shared__ float Bs[BK][BN];

    const int by = blockIdx.y;   // row tile (anchor rows)
    const int bx = blockIdx.x;   // col tile
    const int tid = threadIdx.x;
    const int tr = tid >> 4;     // 0..15
    const int tc = tid & 15;     // 0..15

    const float* Abase = g_fn + (size_t)by * BM * DD;
    const float* Bbase = g_fn + (size_t)bx * BN * DD;

    // loader mapping: 256 threads, each loads 2 x float4 per operand tile
    const int lr = tid >> 2;          // 0..63
    const int lc = (tid & 3) * 4;     // 0,4,8,12

    float acc[TM][TN];
#pragma unroll
    for (int m = 0; m < TM; m++)
#pragma unroll
        for (int n = 0; n < TN; n++)
            acc[m][n] = 0.f;

    for (int k0 = 0; k0 < DD; k0 += BK) {
#pragma unroll
        for (int h = 0; h < 2; h++) {
            int row = lr + h * 64;
            float4 a = *(const float4*)(Abase + (size_t)row * DD + k0 + lc);
            As[lc + 0][row] = a.x; As[lc + 1][row] = a.y;
            As[lc + 2][row] = a.z; As[lc + 3][row] = a.w;
            float4 b = *(const float4*)(Bbase + (size_t)row * DD + k0 + lc);
            Bs[lc + 0][row] = b.x; Bs[lc + 1][row] = b.y;
            Bs[lc + 2][row] = b.z; Bs[lc + 3][row] = b.w;
        }
        __syncthreads();
#pragma unroll
        for (int kk = 0; kk < BK; kk++) {
            float ar[TM], br[TN];
#pragma unroll
            for (int m = 0; m < TM; m++) ar[m] = As[kk][tr * TM + m];
#pragma unroll
            for (int n = 0; n < TN; n++) br[n] = Bs[kk][tc * TN + n];
#pragma unroll
            for (int m = 0; m < TM; m++)
#pragma unroll
                for (int n = 0; n < TN; n++)
                    acc[m][n] = fmaf(ar[m], br[n], acc[m][n]);
        }
        __syncthreads();
    }

    // write (scaled by 1/temperature)
#pragma unroll
    for (int m = 0; m < TM; m++) {
        int gi = by * BM + tr * TM + m;
        float* Crow = g_S + (size_t)gi * N + bx * BN + tc * TN;
#pragma unroll
        for (int n = 0; n < TN; n += 4) {
            float4 w;
            w.x = acc[m][n + 0] * INV_T;
            w.y = acc[m][n + 1] * INV_T;
            w.z = acc[m][n + 2] * INV_T;
            w.w = acc[m][n + 3] * INV_T;
            *(float4*)(Crow + n) = w;
        }
    }
}

// ---------------------------------------------------------------
// Kernel 3: per-anchor epilogue. One block per row.
// Loads the 32KB S-row + packed (label|invalid) bytes into SMEM,
// then 3 sweeps: neg-max, neg-sumexp, positive CE sum.
// Writes per-row (value, flag) -- no atomics, deterministic.
// ---------------------------------------------------------------
__global__ __launch_bounds__(256)
void row_loss_kernel(const int* __restrict__ labels,
                     const int* __restrict__ bad, int N) {
    __shared__ float srow[NN];       // 32 KB
    __shared__ int8_t slab[NN];      // 8 KB: label 0..2, or 3 if invalid
    __shared__ float red[256];
    __shared__ int   redi[256];

    const int i = blockIdx.x;
    const int tid = threadIdx.x;
    const float* Srow = g_S + (size_t)i * N;

    // load row (vectorized) + packed labels
    for (int j = tid * 4; j < N; j += 256 * 4)
        *(float4*)(srow + j) = *(const float4*)(Srow + j);
    for (int j = tid; j < N; j += 256) {
        int lj = labels[j];
        slab[j] = (int8_t)((bad[j] == 0) ? lj : 3);
    }
    __syncthreads();

    const int8_t li = (int8_t)labels[i];
    const bool valid_i = (bad[i] == 0);

    // sweep 1: negative max, positive count
    float mx = -INFINITY;
    int pcnt = 0;
    for (int j = tid; j < N; j += 256) {
        int8_t lj = slab[j];
        float s = srow[j];
        if (lj != 3) {
            if (lj != li) mx = fmaxf(mx, s);
            else if (j != i) pcnt++;
        }
    }
    red[tid] = mx; redi[tid] = pcnt;
    __syncthreads();
    for (int o = 128; o > 0; o >>= 1) {
        if (tid < o) {
            red[tid]  = fmaxf(red[tid], red[tid + o]);
            redi[tid] += redi[tid + o];
        }
        __syncthreads();
    }
    const float negmax = red[0];
    const int pos_cnt  = redi[0];
    const bool has_neg = (negmax > -INFINITY);
    const bool has_pos = (pos_cnt > 0);
    const bool processed = valid_i && has_neg;
    __syncthreads();

    if (!processed) {
        if (tid == 0) { g_rowval[i] = 0.f; g_rowflag[i] = 0; }
        return;
    }

    // sweep 2: sum exp(S - negmax) over negatives
    float se = 0.f;
    for (int j = tid; j < N; j += 256) {
        int8_t lj = slab[j];
        if (lj != 3 && lj != li) se += expf(srow[j] - negmax);
    }
    red[tid] = se;
    __syncthreads();
    for (int o = 128; o > 0; o >>= 1) {
        if (tid < o) red[tid] += red[tid + o];
        __syncthreads();
    }
    const float neg_lse = negmax + logf(red[0]);
    __syncthreads();

    float val;
    if (has_pos) {
        // sweep 3: sum over positives of log1p(exp(neg_lse - S_ip))
        float ps = 0.f;
        for (int j = tid; j < N; j += 256) {
            int8_t lj = slab[j];
            if (lj == li && lj != 3 && j != i) {
                float x = neg_lse - srow[j];
                ps += (x > 0.f) ? (x + log1pf(expf(-x))) : log1pf(expf(x));
            }
        }
        red[tid] = ps;
        __syncthreads();
        for (int o = 128; o > 0; o >>= 1) {
            if (tid < o) red[tid] += red[tid + o];
            __syncthreads();
        }
        val = red[0] / (float)pos_cnt;
    } else {
        float x = neg_lse - INV_T;
        val = (x > 0.f) ? (x + log1pf(expf(-x))) : log1pf(expf(x));
    }

    if (tid == 0) {
        g_rowval[i]  = val;
        g_rowflag[i] = has_pos ? 1 : 0;
    }
}

// ---------------------------------------------------------------
// Kernel 4: final reduction -> out[0] = total / (1 + count)
// ---------------------------------------------------------------
__global__ __launch_bounds__(1024)
void finalize_kernel(float* __restrict__ out, int N) {
    __shared__ float ssum[1024];
    __shared__ int   scnt[1024];
    int tid = threadIdx.x;
    float s = 0.f; int c = 0;
    for (int i = tid; i < N; i += 1024) {
        s += g_rowval[i];
        c += g_rowflag[i];
    }
    ssum[tid] = s; scnt[tid] = c;
    __syncthreads();
    for (int o = 512; o > 0; o >>= 1) {
        if (tid < o) { ssum[tid] += ssum[tid + o]; scnt[tid] += scnt[tid + o]; }
        __syncthreads();
    }
    if (tid == 0) out[0] = ssum[0] / (float)(1 + scnt[0]);
}

// ---------------------------------------------------------------
extern "C" void kernel_launch(void* const* d_in, const int* in_sizes, int n_in,
                              void* d_out, int out_size) {
    const float* feats  = (const float*)d_in[0];
    const int*   labels = (const int*)d_in[1];
    const int*   bad    = (const int*)d_in[2];
    float*       out    = (float*)d_out;

    const int N = in_sizes[1];   // 8192

    normalize_kernel<<<N / 8, 256>>>(feats, N);
    dim3 ggrid(N / BN, N / BM);
    gemm_kernel<<<ggrid, 256>>>(N);
    row_loss_kernel<<<N, 256>>>(labels, bad, N);
    finalize_kernel<<<1, 1024>>>(out, N);
}

// round 10
// speedup vs baseline: 2.6538x; 2.6538x over previous
#include <cuda_runtime.h>
#include <math.h>
#include <stdint.h>

// Problem constants (fixed by the reference setup_inputs()).
#define NN 8192
#define DD 512
#define INV_T 10.0f

// -------- scratch (allocation-free: __device__ globals) --------
__device__ float g_fn[(size_t)NN * DD];           // normalized features (tf32-rounded), 16 MB
__device__ float g_S[(size_t)NN * NN];            // similarity logits, 256 MB
__device__ float g_rowval[NN];                    // per-anchor loss contribution
__device__ int   g_rowflag[NN];                   // processed && has_pos

// ================= helpers =================
__device__ __forceinline__ uint32_t smem_u32(const void* p) {
    return (uint32_t)__cvta_generic_to_shared(p);
}

#define CP_ASYNC16(dst, src) \
    asm volatile("cp.async.cg.shared.global [%0], [%1], 16;" :: "r"(dst), "l"(src) : "memory")
#define CP_COMMIT() asm volatile("cp.async.commit_group;" ::: "memory")
#define CP_WAIT2()  asm volatile("cp.async.wait_group 2;" ::: "memory")
#define CP_WAIT0()  asm volatile("cp.async.wait_group 0;" ::: "memory")

// m16n8k8 tf32 mma (sm_80+, valid in compute_103 PTX)
__device__ __forceinline__ void mma_tf32(float* d, const uint32_t* a, const uint32_t* b) {
    asm volatile(
        "mma.sync.aligned.m16n8k8.row.col.f32.tf32.tf32.f32 "
        "{%0,%1,%2,%3}, {%4,%5,%6,%7}, {%8,%9}, {%0,%1,%2,%3};"
        : "+f"(d[0]), "+f"(d[1]), "+f"(d[2]), "+f"(d[3])
        : "r"(a[0]), "r"(a[1]), "r"(a[2]), "r"(a[3]), "r"(b[0]), "r"(b[1]));
}

// ---------------------------------------------------------------
// Kernel 1: row-normalize + round-to-nearest tf32. One warp per row.
// ---------------------------------------------------------------
__global__ void normalize_kernel(const float* __restrict__ feats, int N) {
    int row  = blockIdx.x * (blockDim.x >> 5) + (threadIdx.x >> 5);
    int lane = threadIdx.x & 31;
    if (row >= N) return;
    const float* src = feats + (size_t)row * DD;
    float v[16];
    float ss = 0.f;
#pragma unroll
    for (int i = 0; i < 16; i++) {
        v[i] = src[lane + i * 32];
        ss += v[i] * v[i];
    }
#pragma unroll
    for (int o = 16; o > 0; o >>= 1)
        ss += __shfl_xor_sync(0xffffffffu, ss, o);
    float inv = 1.0f / sqrtf(ss);
    float* dst = g_fn + (size_t)row * DD;
#pragma unroll
    for (int i = 0; i < 16; i++) {
        float x = v[i] * inv;
        uint32_t u;
        asm("cvt.rna.tf32.f32 %0, %1;" : "=r"(u) : "f"(x));
        dst[lane + i * 32] = __uint_as_float(u);
    }
}

// ---------------------------------------------------------------
// Kernel 2: S = (fn @ fn^T) * INV_T via mma.sync tf32.
// 512 threads, BM=128, BN=256, warp tile 64x32 (warps 2m x 8n).
// K chunks of 32 floats, 3-stage cp.async pipeline.
// SMEM tiles stored [row][k] with row stride 36 floats (conflict-free).
// ---------------------------------------------------------------
#define BMg 128
#define BNg 256
#define KC 32
#define NCHUNK (DD / KC)            // 16
#define RS 36                        // row stride in floats
#define A_FLOATS (BMg * RS)          // 4608
#define B_FLOATS (BNg * RS)          // 9216
#define STAGE_FLOATS (A_FLOATS + B_FLOATS)   // 13824 (55296 B)
#define NSTAGE 3
#define GEMM_SMEM (NSTAGE * STAGE_FLOATS * 4)

extern __shared__ float smemf[];

__global__ __launch_bounds__(512, 1) void gemm_mma_kernel() {
    const int tid  = threadIdx.x;
    const int wid  = tid >> 5;
    const int lane = tid & 31;
    const int wm = wid & 1;           // warp row (x64)
    const int wn = wid >> 1;          // warp col (x32)
    const int g  = lane >> 2;         // group id 0..7
    const int t  = lane & 3;          // thread-in-group

    const int bx = blockIdx.x;        // column tile (BNg)
    const int by = blockIdx.y;        // row tile (BMg)

    const uint32_t sbase = smem_u32(smemf);
    const float* Ab = g_fn + (size_t)by * BMg * DD;
    const float* Bb = g_fn + (size_t)bx * BNg * DD;

    float acc[4][4][4];
#pragma unroll
    for (int mt = 0; mt < 4; mt++)
#pragma unroll
        for (int nt = 0; nt < 4; nt++)
#pragma unroll
            for (int e = 0; e < 4; e++)
                acc[mt][nt][e] = 0.f;

#define LOAD_CHUNK(k) do {                                                     \
        int s_ = (k) % NSTAGE;                                                 \
        uint32_t sA_ = sbase + (uint32_t)(s_ * STAGE_FLOATS * 4);              \
        uint32_t sB_ = sA_ + A_FLOATS * 4;                                     \
        int k0_ = (k) * KC;                                                    \
        _Pragma("unroll")                                                      \
        for (int i_ = 0; i_ < 2; i_++) {                                       \
            int idx_ = tid + i_ * 512;                                         \
            int r_ = idx_ >> 3, c_ = idx_ & 7;                                 \
            CP_ASYNC16(sA_ + (uint32_t)(r_ * RS * 4 + c_ * 16),                \
                       Ab + (size_t)r_ * DD + k0_ + c_ * 4);                   \
        }                                                                      \
        _Pragma("unroll")                                                      \
        for (int i_ = 0; i_ < 4; i_++) {                                       \
            int idx_ = tid + i_ * 512;                                         \
            int r_ = idx_ >> 3, c_ = idx_ & 7;                                 \
            CP_ASYNC16(sB_ + (uint32_t)(r_ * RS * 4 + c_ * 16),                \
                       Bb + (size_t)r_ * DD + k0_ + c_ * 4);                   \
        }                                                                      \
        CP_COMMIT();                                                           \
    } while (0)

    LOAD_CHUNK(0);
    LOAD_CHUNK(1);

    for (int k = 0; k < NCHUNK; k++) {
        if (k + 2 < NCHUNK) LOAD_CHUNK(k + 2);
        if (k + 2 < NCHUNK) { CP_WAIT2(); } else { CP_WAIT0(); }
        __syncthreads();

        const int s = k % NSTAGE;
        const float* As = smemf + s * STAGE_FLOATS;
        const float* Bs = As + A_FLOATS;
        // per-thread fragment bases
        const uint32_t* Arow0 = (const uint32_t*)(As + (wm * 64 + g) * RS + t);
        const uint32_t* Brow0 = (const uint32_t*)(Bs + (wn * 32 + g) * RS + t);

#pragma unroll
        for (int kk = 0; kk < 4; kk++) {
            uint32_t afr[4][4];
#pragma unroll
            for (int mt = 0; mt < 4; mt++) {
                const uint32_t* ap = Arow0 + (mt * 16) * RS + kk * 8;
                afr[mt][0] = ap[0];
                afr[mt][1] = ap[8 * RS];
                afr[mt][2] = ap[4];
                afr[mt][3] = ap[8 * RS + 4];
            }
#pragma unroll
            for (int nt = 0; nt < 4; nt++) {
                const uint32_t* bp = Brow0 + (nt * 8) * RS + kk * 8;
                uint32_t bfr[2];
                bfr[0] = bp[0];
                bfr[1] = bp[4];
#pragma unroll
                for (int mt = 0; mt < 4; mt++)
                    mma_tf32(acc[mt][nt], afr[mt], bfr);
            }
        }
        __syncthreads();
    }

    // --- epilogue: write 64x32 warp tile, scaled by 1/T ---
#pragma unroll
    for (int mt = 0; mt < 4; mt++) {
        int gi0 = by * BMg + wm * 64 + mt * 16 + g;
        float* r0 = g_S + (size_t)gi0 * NN + bx * BNg + wn * 32;
        float* r1 = r0 + (size_t)8 * NN;
#pragma unroll
        for (int nt = 0; nt < 4; nt++) {
            float2 w0, w1;
            w0.x = acc[mt][nt][0] * INV_T; w0.y = acc[mt][nt][1] * INV_T;
            w1.x = acc[mt][nt][2] * INV_T; w1.y = acc[mt][nt][3] * INV_T;
            *(float2*)(r0 + nt * 8 + 2 * t) = w0;
            *(float2*)(r1 + nt * 8 + 2 * t) = w1;
        }
    }
}

// ---------------------------------------------------------------
// Kernel 3: per-anchor epilogue. One block per row.
// ---------------------------------------------------------------
__global__ __launch_bounds__(256)
void row_loss_kernel(const int* __restrict__ labels,
                     const int* __restrict__ bad, int N) {
    __shared__ float srow[NN];       // 32 KB
    __shared__ int8_t slab[NN];      // 8 KB
    __shared__ float red[256];
    __shared__ int   redi[256];

    const int i = blockIdx.x;
    const int tid = threadIdx.x;
    const float* Srow = g_S + (size_t)i * N;

    for (int j = tid * 4; j < N; j += 256 * 4)
        *(float4*)(srow + j) = *(const float4*)(Srow + j);
    for (int j = tid; j < N; j += 256) {
        int lj = labels[j];
        slab[j] = (int8_t)((bad[j] == 0) ? lj : 3);
    }
    __syncthreads();

    const int8_t li = (int8_t)labels[i];
    const bool valid_i = (bad[i] == 0);

    float mx = -INFINITY;
    int pcnt = 0;
    for (int j = tid; j < N; j += 256) {
        int8_t lj = slab[j];
        float s = srow[j];
        if (lj != 3) {
            if (lj != li) mx = fmaxf(mx, s);
            else if (j != i) pcnt++;
        }
    }
    red[tid] = mx; redi[tid] = pcnt;
    __syncthreads();
    for (int o = 128; o > 0; o >>= 1) {
        if (tid < o) {
            red[tid]  = fmaxf(red[tid], red[tid + o]);
            redi[tid] += redi[tid + o];
        }
        __syncthreads();
    }
    const float negmax = red[0];
    const int pos_cnt  = redi[0];
    const bool has_neg = (negmax > -INFINITY);
    const bool has_pos = (pos_cnt > 0);
    const bool processed = valid_i && has_neg;
    __syncthreads();

    if (!processed) {
        if (tid == 0) { g_rowval[i] = 0.f; g_rowflag[i] = 0; }
        return;
    }

    float se = 0.f;
    for (int j = tid; j < N; j += 256) {
        int8_t lj = slab[j];
        if (lj != 3 && lj != li) se += expf(srow[j] - negmax);
    }
    red[tid] = se;
    __syncthreads();
    for (int o = 128; o > 0; o >>= 1) {
        if (tid < o) red[tid] += red[tid + o];
        __syncthreads();
    }
    const float neg_lse = negmax + logf(red[0]);
    __syncthreads();

    float val;
    if (has_pos) {
        float ps = 0.f;
        for (int j = tid; j < N; j += 256) {
            int8_t lj = slab[j];
            if (lj == li && lj != 3 && j != i) {
                float x = neg_lse - srow[j];
                ps += (x > 0.f) ? (x + log1pf(expf(-x))) : log1pf(expf(x));
            }
        }
        red[tid] = ps;
        __syncthreads();
        for (int o = 128; o > 0; o >>= 1) {
            if (tid < o) red[tid] += red[tid + o];
            __syncthreads();
        }
        val = red[0] / (float)pos_cnt;
    } else {
        float x = neg_lse - INV_T;
        val = (x > 0.f) ? (x + log1pf(expf(-x))) : log1pf(expf(x));
    }

    if (tid == 0) {
        g_rowval[i]  = val;
        g_rowflag[i] = has_pos ? 1 : 0;
    }
}

// ---------------------------------------------------------------
// Kernel 4: final reduction -> out[0] = total / (1 + count)
// ---------------------------------------------------------------
__global__ __launch_bounds__(1024)
void finalize_kernel(float* __restrict__ out, int N) {
    __shared__ float ssum[1024];
    __shared__ int   scnt[1024];
    int tid = threadIdx.x;
    float s = 0.f; int c = 0;
    for (int i = tid; i < N; i += 1024) {
        s += g_rowval[i];
        c += g_rowflag[i];
    }
    ssum[tid] = s; scnt[tid] = c;
    __syncthreads();
    for (int o = 512; o > 0; o >>= 1) {
        if (tid < o) { ssum[tid] += ssum[tid + o]; scnt[tid] += scnt[tid + o]; }
        __syncthreads();
    }
    if (tid == 0) out[0] = ssum[0] / (float)(1 + scnt[0]);
}

// ---------------------------------------------------------------
extern "C" void kernel_launch(void* const* d_in, const int* in_sizes, int n_in,
                              void* d_out, int out_size) {
    const float* feats  = (const float*)d_in[0];
    const int*   labels = (const int*)d_in[1];
    const int*   bad    = (const int*)d_in[2];
    float*       out    = (float*)d_out;

    const int N = in_sizes[1];   // 8192

    static int smem_set = 0;
    if (!smem_set) {
        cudaFuncSetAttribute(gemm_mma_kernel,
                             cudaFuncAttributeMaxDynamicSharedMemorySize, GEMM_SMEM);
        smem_set = 1;
    }

    normalize_kernel<<<N / 8, 256>>>(feats, N);
    dim3 ggrid(N / BNg, N / BMg);   // (32, 64)
    gemm_mma_kernel<<<ggrid, 512, GEMM_SMEM>>>();
    row_loss_kernel<<<N, 256>>>(labels, bad, N);
    finalize_kernel<<<1, 1024>>>(out, N);
}

// round 11
// speedup vs baseline: 3.7694x; 1.4204x over previous
#include <cuda_runtime.h>
#include <cuda_fp16.h>
#include <math.h>
#include <stdint.h>

// Problem constants (fixed by the reference setup_inputs()).
#define NN 8192
#define DD 512
#define INV_T 10.0f

// -------- scratch (allocation-free: __device__ globals) --------
__device__ __half g_fnh[(size_t)NN * DD];         // normalized features (fp16), 8 MB
__device__ float  g_S[(size_t)NN * NN];           // similarity logits, 256 MB
__device__ float  g_rowval[NN];
__device__ int    g_rowflag[NN];

// ================= helpers =================
__device__ __forceinline__ uint32_t smem_u32(const void* p) {
    return (uint32_t)__cvta_generic_to_shared(p);
}

#define CP_ASYNC16(dst, src) \
    asm volatile("cp.async.cg.shared.global [%0], [%1], 16;" :: "r"(dst), "l"(src) : "memory")
#define CP_COMMIT() asm volatile("cp.async.commit_group;" ::: "memory")
#define CP_WAIT2()  asm volatile("cp.async.wait_group 2;" ::: "memory")
#define CP_WAIT0()  asm volatile("cp.async.wait_group 0;" ::: "memory")

#define LDMATRIX_X4(r0, r1, r2, r3, addr) \
    asm volatile("ldmatrix.sync.aligned.m8n8.x4.shared.b16 {%0,%1,%2,%3}, [%4];" \
                 : "=r"(r0), "=r"(r1), "=r"(r2), "=r"(r3) : "r"(addr))

// m16n8k16 fp16 mma, fp32 accumulate (sm_80+, valid in compute_103 PTX)
__device__ __forceinline__ void mma_f16(float* d, const uint32_t* a, uint32_t b0, uint32_t b1) {
    asm volatile(
        "mma.sync.aligned.m16n8k16.row.col.f32.f16.f16.f32 "
        "{%0,%1,%2,%3}, {%4,%5,%6,%7}, {%8,%9}, {%0,%1,%2,%3};"
        : "+f"(d[0]), "+f"(d[1]), "+f"(d[2]), "+f"(d[3])
        : "r"(a[0]), "r"(a[1]), "r"(a[2]), "r"(a[3]), "r"(b0), "r"(b1));
}

// ---------------------------------------------------------------
// Kernel 1: row-normalize -> fp16. One warp per row.
// Lane handles 8 float2 pairs (cols 2*lane + 64*i), writes half2.
// ---------------------------------------------------------------
__global__ void normalize_kernel(const float* __restrict__ feats, int N) {
    int row  = blockIdx.x * (blockDim.x >> 5) + (threadIdx.x >> 5);
    int lane = threadIdx.x & 31;
    if (row >= N) return;
    const float2* src = (const float2*)(feats + (size_t)row * DD);
    float2 v[8];
    float ss = 0.f;
#pragma unroll
    for (int i = 0; i < 8; i++) {
        v[i] = src[lane + i * 32];
        ss += v[i].x * v[i].x + v[i].y * v[i].y;
    }
#pragma unroll
    for (int o = 16; o > 0; o >>= 1)
        ss += __shfl_xor_sync(0xffffffffu, ss, o);
    float inv = 1.0f / sqrtf(ss);
    __half2* dst = (__half2*)(g_fnh + (size_t)row * DD);
#pragma unroll
    for (int i = 0; i < 8; i++)
        dst[lane + i * 32] = __floats2half2_rn(v[i].x * inv, v[i].y * inv);
}

// ---------------------------------------------------------------
// Kernel 2: S = (fn @ fn^T) * INV_T via mma.sync m16n8k16 fp16.
// 512 threads, BM=128, BN=256, warp tile 64x32 (warps 2m x 8n).
// K chunks of 32 halves; 3-stage cp.async pipeline.
// SMEM rows padded to 40 halves (80 B) -> ldmatrix conflict-free.
// ---------------------------------------------------------------
#define BMg 128
#define BNg 256
#define KC 32
#define NCHUNK (DD / KC)             // 16
#define RSH 40                        // row stride in halves (80 B)
#define A_BYTES (BMg * RSH * 2)       // 10240
#define B_BYTES (BNg * RSH * 2)       // 20480
#define STAGE_BYTES (A_BYTES + B_BYTES)   // 30720
#define NSTAGE 3
#define GEMM_SMEM (NSTAGE * STAGE_BYTES)  // 92160

extern __shared__ char smemc[];

__global__ __launch_bounds__(512, 1) void gemm_mma_kernel() {
    const int tid  = threadIdx.x;
    const int wid  = tid >> 5;
    const int lane = tid & 31;
    const int wm = wid & 1;           // warp row (x64)
    const int wn = wid >> 1;          // warp col (x32)
    const int g  = lane >> 2;         // group id 0..7
    const int t  = lane & 3;          // thread-in-group

    const int bx = blockIdx.x;        // column tile (BNg)
    const int by = blockIdx.y;        // row tile (BMg)

    const uint32_t sbase = smem_u32(smemc);
    const __half* Ab = g_fnh + (size_t)by * BMg * DD;
    const __half* Bb = g_fnh + (size_t)bx * BNg * DD;

    // ldmatrix per-lane row/col selectors
    const int aRow  = (lane & 7) + ((lane >> 3) & 1) * 8;   // A: matrices {r0-7,k0-7},{r8-15,k0-7},{r0-7,k8-15},{r8-15,k8-15}
    const int aC8   = (lane >> 4) & 1;
    const int bRow  = (lane & 7) + ((lane >> 4) & 1) * 8;   // B: {n0-7,k0-7},{n0-7,k8-15},{n8-15,k0-7},{n8-15,k8-15}
    const int bK8   = (lane >> 3) & 1;
    const uint32_t aoff = (uint32_t)(((wm * 64 + aRow) * RSH + aC8 * 8) * 2);
    const uint32_t boff = (uint32_t)(((wn * 32 + bRow) * RSH + bK8 * 8) * 2);

    float acc[4][4][4];
#pragma unroll
    for (int mt = 0; mt < 4; mt++)
#pragma unroll
        for (int nt = 0; nt < 4; nt++)
#pragma unroll
            for (int e = 0; e < 4; e++)
                acc[mt][nt][e] = 0.f;

#define LOAD_CHUNK(k) do {                                                     \
        int s_ = (k) % NSTAGE;                                                 \
        uint32_t sA_ = sbase + (uint32_t)(s_ * STAGE_BYTES);                   \
        uint32_t sB_ = sA_ + A_BYTES;                                          \
        int k0_ = (k) * KC;                                                    \
        { int r_ = tid >> 2, c_ = tid & 3;                                     \
          CP_ASYNC16(sA_ + (uint32_t)(r_ * 80 + c_ * 16),                      \
                     Ab + (size_t)r_ * DD + k0_ + c_ * 8); }                   \
        _Pragma("unroll")                                                      \
        for (int i_ = 0; i_ < 2; i_++) {                                       \
            int idx_ = tid + i_ * 512;                                         \
            int r_ = idx_ >> 2, c_ = idx_ & 3;                                 \
            CP_ASYNC16(sB_ + (uint32_t)(r_ * 80 + c_ * 16),                    \
                       Bb + (size_t)r_ * DD + k0_ + c_ * 8);                   \
        }                                                                      \
        CP_COMMIT();                                                           \
    } while (0)

    LOAD_CHUNK(0);
    LOAD_CHUNK(1);

    for (int k = 0; k < NCHUNK; k++) {
        if (k + 2 < NCHUNK) LOAD_CHUNK(k + 2);
        if (k + 2 < NCHUNK) { CP_WAIT2(); } else { CP_WAIT0(); }
        __syncthreads();

        const int s = k % NSTAGE;
        const uint32_t sA = sbase + (uint32_t)(s * STAGE_BYTES) + aoff;
        const uint32_t sB = sbase + (uint32_t)(s * STAGE_BYTES) + A_BYTES + boff;

#pragma unroll
        for (int kk = 0; kk < 2; kk++) {
            uint32_t a[4][4];
#pragma unroll
            for (int mt = 0; mt < 4; mt++)
                LDMATRIX_X4(a[mt][0], a[mt][1], a[mt][2], a[mt][3],
                            sA + (uint32_t)(mt * 16 * 80 + kk * 32));
            uint32_t b[2][4];
#pragma unroll
            for (int np = 0; np < 2; np++)
                LDMATRIX_X4(b[np][0], b[np][1], b[np][2], b[np][3],
                            sB + (uint32_t)(np * 16 * 80 + kk * 32));
#pragma unroll
            for (int mt = 0; mt < 4; mt++) {
#pragma unroll
                for (int np = 0; np < 2; np++) {
                    mma_f16(acc[mt][np * 2 + 0], a[mt], b[np][0], b[np][1]);
                    mma_f16(acc[mt][np * 2 + 1], a[mt], b[np][2], b[np][3]);
                }
            }
        }
        __syncthreads();
    }

    // --- epilogue: write 64x32 warp tile, scaled by 1/T ---
#pragma unroll
    for (int mt = 0; mt < 4; mt++) {
        int gi0 = by * BMg + wm * 64 + mt * 16 + g;
        float* r0 = g_S + (size_t)gi0 * NN + bx * BNg + wn * 32;
        float* r1 = r0 + (size_t)8 * NN;
#pragma unroll
        for (int nt = 0; nt < 4; nt++) {
            float2 w0, w1;
            w0.x = acc[mt][nt][0] * INV_T; w0.y = acc[mt][nt][1] * INV_T;
            w1.x = acc[mt][nt][2] * INV_T; w1.y = acc[mt][nt][3] * INV_T;
            *(float2*)(r0 + nt * 8 + 2 * t) = w0;
            *(float2*)(r1 + nt * 8 + 2 * t) = w1;
        }
    }
}

// ---------------------------------------------------------------
// Kernel 3: per-anchor epilogue. One block per row.
// Sweep A (fused): online logsumexp over negatives + positive count.
// Sweep B: positive softplus sum.
// ---------------------------------------------------------------
__global__ __launch_bounds__(256)
void row_loss_kernel(const int* __restrict__ labels,
                     const int* __restrict__ bad, int N) {
    __shared__ float srow[NN];       // 32 KB
    __shared__ int8_t slab[NN];      // 8 KB
    __shared__ float redm[256];
    __shared__ float reds[256];
    __shared__ int   redi[256];

    const int i = blockIdx.x;
    const int tid = threadIdx.x;
    const float* Srow = g_S + (size_t)i * N;

    for (int j = tid * 4; j < N; j += 256 * 4)
        *(float4*)(srow + j) = *(const float4*)(Srow + j);
    for (int j = tid; j < N; j += 256) {
        int lj = labels[j];
        slab[j] = (int8_t)((bad[j] == 0) ? lj : 3);
    }
    __syncthreads();

    const int8_t li = (int8_t)labels[i];
    const bool valid_i = (bad[i] == 0);

    // fused sweep: per-thread online LSE over negatives + pos count
    float m = -INFINITY, sum = 0.f;
    int pcnt = 0;
    for (int j = tid; j < N; j += 256) {
        int8_t lj = slab[j];
        if (lj != 3) {
            if (lj != li) {
                float v = srow[j];
                if (v > m) { sum = sum * expf(m - v) + 1.f; m = v; }
                else       { sum += expf(v - m); }
            } else if (j != i) pcnt++;
        }
    }
    redm[tid] = m; reds[tid] = sum; redi[tid] = pcnt;
    __syncthreads();
    for (int o = 128; o > 0; o >>= 1) {
        if (tid < o) {
            float m2 = redm[tid + o], s2 = reds[tid + o];
            float m1 = redm[tid],     s1 = reds[tid];
            if (m2 > m1) { float tm = m1; m1 = m2; m2 = tm;
                           float ts = s1; s1 = s2; s2 = ts; }
            // m1 >= m2; if m2 == -inf its sum contributes 0
            if (m2 > -INFINITY) s1 += s2 * expf(m2 - m1);
            redm[tid] = m1; reds[tid] = s1;
            redi[tid] += redi[tid + o];
        }
        __syncthreads();
    }
    const float negmax = redm[0];
    const float negsum = reds[0];
    const int pos_cnt  = redi[0];
    const bool has_neg = (negmax > -INFINITY);
    const bool has_pos = (pos_cnt > 0);
    const bool processed = valid_i && has_neg;
    __syncthreads();

    if (!processed) {
        if (tid == 0) { g_rowval[i] = 0.f; g_rowflag[i] = 0; }
        return;
    }
    const float neg_lse = negmax + logf(negsum);

    float val;
    if (has_pos) {
        float ps = 0.f;
        for (int j = tid; j < N; j += 256) {
            int8_t lj = slab[j];
            if (lj == li && j != i) {
                float x = neg_lse - srow[j];
                ps += (x > 0.f) ? (x + log1pf(expf(-x))) : log1pf(expf(x));
            }
        }
        reds[tid] = ps;
        __syncthreads();
        for (int o = 128; o > 0; o >>= 1) {
            if (tid < o) reds[tid] += reds[tid + o];
            __syncthreads();
        }
        val = reds[0] / (float)pos_cnt;
    } else {
        float x = neg_lse - INV_T;
        val = (x > 0.f) ? (x + log1pf(expf(-x))) : log1pf(expf(x));
    }

    if (tid == 0) {
        g_rowval[i]  = val;
        g_rowflag[i] = has_pos ? 1 : 0;
    }
}

// ---------------------------------------------------------------
// Kernel 4: final reduction -> out[0] = total / (1 + count)
// ---------------------------------------------------------------
__global__ __launch_bounds__(1024)
void finalize_kernel(float* __restrict__ out, int N) {
    __shared__ float ssum[1024];
    __shared__ int   scnt[1024];
    int tid = threadIdx.x;
    float s = 0.f; int c = 0;
    for (int i = tid; i < N; i += 1024) {
        s += g_rowval[i];
        c += g_rowflag[i];
    }
    ssum[tid] = s; scnt[tid] = c;
    __syncthreads();
    for (int o = 512; o > 0; o >>= 1) {
        if (tid < o) { ssum[tid] += ssum[tid + o]; scnt[tid] += scnt[tid + o]; }
        __syncthreads();
    }
    if (tid == 0) out[0] = ssum[0] / (float)(1 + scnt[0]);
}

// ---------------------------------------------------------------
extern "C" void kernel_launch(void* const* d_in, const int* in_sizes, int n_in,
                              void* d_out, int out_size) {
    const float* feats  = (const float*)d_in[0];
    const int*   labels = (const int*)d_in[1];
    const int*   bad    = (const int*)d_in[2];
    float*       out    = (float*)d_out;

    const int N = in_sizes[1];   // 8192

    static int smem_set = 0;
    if (!smem_set) {
        cudaFuncSetAttribute(gemm_mma_kernel,
                             cudaFuncAttributeMaxDynamicSharedMemorySize, GEMM_SMEM);
        smem_set = 1;
    }

    normalize_kernel<<<N / 8, 256>>>(feats, N);
    dim3 ggrid(N / BNg, N / BMg);   // (32, 64)
    gemm_mma_kernel<<<ggrid, 512, GEMM_SMEM>>>();
    row_loss_kernel<<<N, 256>>>(labels, bad, N);
    finalize_kernel<<<1, 1024>>>(out, N);
}

// round 12
// speedup vs baseline: 4.6947x; 1.2455x over previous
#include <cuda_runtime.h>
#include <cuda_fp16.h>
#include <math.h>
#include <stdint.h>

// Problem constants (fixed by the reference setup_inputs()).
#define NN 8192
#define DD 512
#define INV_T 10.0f

// -------- scratch (allocation-free: __device__ globals) --------
__device__ __half g_fnh[(size_t)NN * DD];         // normalized features (fp16), 8 MB
__device__ float  g_S[(size_t)NN * NN];           // similarity logits, 256 MB
__device__ float  g_rowval[NN];
__device__ int    g_rowflag[NN];

// ================= helpers =================
__device__ __forceinline__ uint32_t smem_u32(const void* p) {
    return (uint32_t)__cvta_generic_to_shared(p);
}

#define CP_ASYNC16(dst, src) \
    asm volatile("cp.async.cg.shared.global [%0], [%1], 16;" :: "r"(dst), "l"(src) : "memory")
#define CP_COMMIT() asm volatile("cp.async.commit_group;" ::: "memory")
#define CP_WAIT1()  asm volatile("cp.async.wait_group 1;" ::: "memory")
#define CP_WAIT0()  asm volatile("cp.async.wait_group 0;" ::: "memory")

#define LDMATRIX_X4(r0, r1, r2, r3, addr) \
    asm volatile("ldmatrix.sync.aligned.m8n8.x4.shared.b16 {%0,%1,%2,%3}, [%4];" \
                 : "=r"(r0), "=r"(r1), "=r"(r2), "=r"(r3) : "r"(addr))

// m16n8k16 fp16 mma, fp32 accumulate
__device__ __forceinline__ void mma_f16(float* d, const uint32_t* a, uint32_t b0, uint32_t b1) {
    asm volatile(
        "mma.sync.aligned.m16n8k16.row.col.f32.f16.f16.f32 "
        "{%0,%1,%2,%3}, {%4,%5,%6,%7}, {%8,%9}, {%0,%1,%2,%3};"
        : "+f"(d[0]), "+f"(d[1]), "+f"(d[2]), "+f"(d[3])
        : "r"(a[0]), "r"(a[1]), "r"(a[2]), "r"(a[3]), "r"(b0), "r"(b1));
}

// ---------------------------------------------------------------
// Kernel 1: row-normalize -> fp16. One warp per row.
// ---------------------------------------------------------------
__global__ void normalize_kernel(const float* __restrict__ feats, int N) {
    int row  = blockIdx.x * (blockDim.x >> 5) + (threadIdx.x >> 5);
    int lane = threadIdx.x & 31;
    if (row >= N) return;
    const float2* src = (const float2*)(feats + (size_t)row * DD);
    float2 v[8];
    float ss = 0.f;
#pragma unroll
    for (int i = 0; i < 8; i++) {
        v[i] = src[lane + i * 32];
        ss += v[i].x * v[i].x + v[i].y * v[i].y;
    }
#pragma unroll
    for (int o = 16; o > 0; o >>= 1)
        ss += __shfl_xor_sync(0xffffffffu, ss, o);
    float inv = 1.0f / sqrtf(ss);
    __half2* dst = (__half2*)(g_fnh + (size_t)row * DD);
#pragma unroll
    for (int i = 0; i < 8; i++)
        dst[lane + i * 32] = __floats2half2_rn(v[i].x * inv, v[i].y * inv);
}

// ---------------------------------------------------------------
// Kernel 2: symmetric GEMM. Only block-upper-triangle tiles
// (by <= 2*bx+1); each tile is written directly AND transposed
// (staged through SMEM). 512 threads, BM=128, BN=256,
// warp tile 64x32, 3-stage cp.async, 1 sync per k-chunk.
// ---------------------------------------------------------------
#define BMg 128
#define BNg 256
#define KC 32
#define NCHUNK (DD / KC)             // 16
#define RSH 40                        // half row stride (80 B)
#define A_BYTES (BMg * RSH * 2)       // 10240
#define B_BYTES (BNg * RSH * 2)       // 20480
#define STAGE_BYTES (A_BYTES + B_BYTES)   // 30720
#define NSTAGE 3
#define TSTRIDE 132                   // transpose staging stride (floats)
#define TRANS_BYTES (128 * TSTRIDE * 4)   // 67584
#define GEMM_SMEM (NSTAGE * STAGE_BYTES)  // 92160 (> TRANS_BYTES, reused)
#define NTILES (32 * 33)              // 1056

extern __shared__ char smemc[];

__global__ __launch_bounds__(512, 1) void gemm_mma_kernel() {
    const int tid  = threadIdx.x;
    const int wid  = tid >> 5;
    const int lane = tid & 31;
    const int wm = wid & 1;           // warp row (x64)
    const int wn = wid >> 1;          // warp col (x32)
    const int g  = lane >> 2;         // group id 0..7
    const int t  = lane & 3;          // thread-in-group

    // decode linear block id -> (bx, by) with by in [0, 2bx+2)
    int id = blockIdx.x;
    int bx = (int)((sqrtf((float)(4 * id + 1)) - 1.f) * 0.5f);
    while ((bx + 1) * (bx + 2) <= id) bx++;
    while (bx * (bx + 1) > id) bx--;
    const int by = id - bx * (bx + 1);

    const uint32_t sbase = smem_u32(smemc);
    const __half* Ab = g_fnh + (size_t)by * BMg * DD;
    const __half* Bb = g_fnh + (size_t)bx * BNg * DD;

    // ldmatrix per-lane selectors
    const int aRow  = (lane & 7) + ((lane >> 3) & 1) * 8;
    const int aC8   = (lane >> 4) & 1;
    const int bRow  = (lane & 7) + ((lane >> 4) & 1) * 8;
    const int bK8   = (lane >> 3) & 1;
    const uint32_t aoff = (uint32_t)(((wm * 64 + aRow) * RSH + aC8 * 8) * 2);
    const uint32_t boff = (uint32_t)(((wn * 32 + bRow) * RSH + bK8 * 8) * 2);

    float acc[4][4][4];
#pragma unroll
    for (int mt = 0; mt < 4; mt++)
#pragma unroll
        for (int nt = 0; nt < 4; nt++)
#pragma unroll
            for (int e = 0; e < 4; e++)
                acc[mt][nt][e] = 0.f;

#define LOAD_CHUNK(k) do {                                                     \
        int s_ = (k) % NSTAGE;                                                 \
        uint32_t sA_ = sbase + (uint32_t)(s_ * STAGE_BYTES);                   \
        uint32_t sB_ = sA_ + A_BYTES;                                          \
        int k0_ = (k) * KC;                                                    \
        { int r_ = tid >> 2, c_ = tid & 3;                                     \
          CP_ASYNC16(sA_ + (uint32_t)(r_ * 80 + c_ * 16),                      \
                     Ab + (size_t)r_ * DD + k0_ + c_ * 8); }                   \
        _Pragma("unroll")                                                      \
        for (int i_ = 0; i_ < 2; i_++) {                                       \
            int idx_ = tid + i_ * 512;                                         \
            int r_ = idx_ >> 2, c_ = idx_ & 3;                                 \
            CP_ASYNC16(sB_ + (uint32_t)(r_ * 80 + c_ * 16),                    \
                       Bb + (size_t)r_ * DD + k0_ + c_ * 8);                   \
        }                                                                      \
        CP_COMMIT();                                                           \
    } while (0)

    LOAD_CHUNK(0);
    LOAD_CHUNK(1);

    for (int k = 0; k < NCHUNK; k++) {
        if (k + 1 < NCHUNK) { CP_WAIT1(); } else { CP_WAIT0(); }
        __syncthreads();
        if (k + 2 < NCHUNK) LOAD_CHUNK(k + 2);   // stage (k+2)%3 == (k-1)%3, retired by barrier

        const int s = k % NSTAGE;
        const uint32_t sA = sbase + (uint32_t)(s * STAGE_BYTES) + aoff;
        const uint32_t sB = sbase + (uint32_t)(s * STAGE_BYTES) + A_BYTES + boff;

#pragma unroll
        for (int kk = 0; kk < 2; kk++) {
            uint32_t a[4][4];
#pragma unroll
            for (int mt = 0; mt < 4; mt++)
                LDMATRIX_X4(a[mt][0], a[mt][1], a[mt][2], a[mt][3],
                            sA + (uint32_t)(mt * 16 * 80 + kk * 32));
            uint32_t b[2][4];
#pragma unroll
            for (int np = 0; np < 2; np++)
                LDMATRIX_X4(b[np][0], b[np][1], b[np][2], b[np][3],
                            sB + (uint32_t)(np * 16 * 80 + kk * 32));
#pragma unroll
            for (int mt = 0; mt < 4; mt++) {
#pragma unroll
                for (int np = 0; np < 2; np++) {
                    mma_f16(acc[mt][np * 2 + 0], a[mt], b[np][0], b[np][1]);
                    mma_f16(acc[mt][np * 2 + 1], a[mt], b[np][2], b[np][3]);
                }
            }
        }
    }

    // --- pre-scale accumulators ---
#pragma unroll
    for (int mt = 0; mt < 4; mt++)
#pragma unroll
        for (int nt = 0; nt < 4; nt++)
#pragma unroll
            for (int e = 0; e < 4; e++)
                acc[mt][nt][e] *= INV_T;

    // --- direct write: tile (rows by*128.., cols bx*256..) ---
#pragma unroll
    for (int mt = 0; mt < 4; mt++) {
        int gi0 = by * BMg + wm * 64 + mt * 16 + g;
        float* r0 = g_S + (size_t)gi0 * NN + bx * BNg + wn * 32;
        float* r1 = r0 + (size_t)8 * NN;
#pragma unroll
        for (int nt = 0; nt < 4; nt++) {
            float2 w0, w1;
            w0.x = acc[mt][nt][0]; w0.y = acc[mt][nt][1];
            w1.x = acc[mt][nt][2]; w1.y = acc[mt][nt][3];
            *(float2*)(r0 + nt * 8 + 2 * t) = w0;
            *(float2*)(r1 + nt * 8 + 2 * t) = w1;
        }
    }

    // --- transposed write via SMEM staging (2 halves of 128 cols) ---
    float* smT = (float*)smemc;
    __syncthreads();   // pipeline stages dead; reuse smem
#pragma unroll
    for (int h = 0; h < 2; h++) {
        if ((wn >> 2) == h) {
            int cw = (wn & 3) * 32;
#pragma unroll
            for (int mt = 0; mt < 4; mt++) {
                int r = wm * 64 + mt * 16 + g;
#pragma unroll
                for (int nt = 0; nt < 4; nt++) {
                    int c = cw + nt * 8 + 2 * t;
                    smT[(size_t)c * TSTRIDE + r]           = acc[mt][nt][0];
                    smT[(size_t)(c + 1) * TSTRIDE + r]     = acc[mt][nt][1];
                    smT[(size_t)c * TSTRIDE + r + 8]       = acc[mt][nt][2];
                    smT[(size_t)(c + 1) * TSTRIDE + r + 8] = acc[mt][nt][3];
                }
            }
        }
        __syncthreads();
        const int colBase = bx * BNg + h * 128;
        const int rowBase = by * BMg;
#pragma unroll
        for (int it = 0; it < 8; it++) {
            int idx = tid + it * 512;       // 0..4095
            int c   = idx >> 5;             // 0..127
            int rq  = (idx & 31) * 4;
            float4 v = *(float4*)(smT + (size_t)c * TSTRIDE + rq);
            *(float4*)(g_S + (size_t)(colBase + c) * NN + rowBase + rq) = v;
        }
        __syncthreads();
    }
}

// ---------------------------------------------------------------
// Kernel 3: per-anchor epilogue. One block per row.
// ---------------------------------------------------------------
__global__ __launch_bounds__(256)
void row_loss_kernel(const int* __restrict__ labels,
                     const int* __restrict__ bad, int N) {
    __shared__ float srow[NN];       // 32 KB
    __shared__ int8_t slab[NN];      // 8 KB
    __shared__ float redm[256];
    __shared__ float reds[256];
    __shared__ int   redi[256];

    const int i = blockIdx.x;
    const int tid = threadIdx.x;
    const float* Srow = g_S + (size_t)i * N;

    for (int j = tid * 4; j < N; j += 256 * 4)
        *(float4*)(srow + j) = *(const float4*)(Srow + j);
    for (int j = tid; j < N; j += 256) {
        int lj = labels[j];
        slab[j] = (int8_t)((bad[j] == 0) ? lj : 3);
    }
    __syncthreads();

    const int8_t li = (int8_t)labels[i];
    const bool valid_i = (bad[i] == 0);

    float m = -INFINITY, sum = 0.f;
    int pcnt = 0;
    for (int j = tid; j < N; j += 256) {
        int8_t lj = slab[j];
        if (lj != 3) {
            if (lj != li) {
                float v = srow[j];
                if (v > m) { sum = sum * expf(m - v) + 1.f; m = v; }
                else       { sum += expf(v - m); }
            } else if (j != i) pcnt++;
        }
    }
    redm[tid] = m; reds[tid] = sum; redi[tid] = pcnt;
    __syncthreads();
    for (int o = 128; o > 0; o >>= 1) {
        if (tid < o) {
            float m2 = redm[tid + o], s2 = reds[tid + o];
            float m1 = redm[tid],     s1 = reds[tid];
            if (m2 > m1) { float tm = m1; m1 = m2; m2 = tm;
                           float ts = s1; s1 = s2; s2 = ts; }
            if (m2 > -INFINITY) s1 += s2 * expf(m2 - m1);
            redm[tid] = m1; reds[tid] = s1;
            redi[tid] += redi[tid + o];
        }
        __syncthreads();
    }
    const float negmax = redm[0];
    const float negsum = reds[0];
    const int pos_cnt  = redi[0];
    const bool has_neg = (negmax > -INFINITY);
    const bool has_pos = (pos_cnt > 0);
    const bool processed = valid_i && has_neg;
    __syncthreads();

    if (!processed) {
        if (tid == 0) { g_rowval[i] = 0.f; g_rowflag[i] = 0; }
        return;
    }
    const float neg_lse = negmax + logf(negsum);

    float val;
    if (has_pos) {
        float ps = 0.f;
        for (int j = tid; j < N; j += 256) {
            int8_t lj = slab[j];
            if (lj == li && j != i) {
                float x = neg_lse - srow[j];
                ps += (x > 0.f) ? (x + log1pf(expf(-x))) : log1pf(expf(x));
            }
        }
        reds[tid] = ps;
        __syncthreads();
        for (int o = 128; o > 0; o >>= 1) {
            if (tid < o) reds[tid] += reds[tid + o];
            __syncthreads();
        }
        val = reds[0] / (float)pos_cnt;
    } else {
        float x = neg_lse - INV_T;
        val = (x > 0.f) ? (x + log1pf(expf(-x))) : log1pf(expf(x));
    }

    if (tid == 0) {
        g_rowval[i]  = val;
        g_rowflag[i] = has_pos ? 1 : 0;
    }
}

// ---------------------------------------------------------------
// Kernel 4: final reduction -> out[0] = total / (1 + count)
// ---------------------------------------------------------------
__global__ __launch_bounds__(1024)
void finalize_kernel(float* __restrict__ out, int N) {
    __shared__ float ssum[1024];
    __shared__ int   scnt[1024];
    int tid = threadIdx.x;
    float s = 0.f; int c = 0;
    for (int i = tid; i < N; i += 1024) {
        s += g_rowval[i];
        c += g_rowflag[i];
    }
    ssum[tid] = s; scnt[tid] = c;
    __syncthreads();
    for (int o = 512; o > 0; o >>= 1) {
        if (tid < o) { ssum[tid] += ssum[tid + o]; scnt[tid] += scnt[tid + o]; }
        __syncthreads();
    }
    if (tid == 0) out[0] = ssum[0] / (float)(1 + scnt[0]);
}

// ---------------------------------------------------------------
extern "C" void kernel_launch(void* const* d_in, const int* in_sizes, int n_in,
                              void* d_out, int out_size) {
    const float* feats  = (const float*)d_in[0];
    const int*   labels = (const int*)d_in[1];
    const int*   bad    = (const int*)d_in[2];
    float*       out    = (float*)d_out;

    const int N = in_sizes[1];   // 8192

    static int smem_set = 0;
    if (!smem_set) {
        cudaFuncSetAttribute(gemm_mma_kernel,
                             cudaFuncAttributeMaxDynamicSharedMemorySize, GEMM_SMEM);
        smem_set = 1;
    }

    normalize_kernel<<<N / 8, 256>>>(feats, N);
    gemm_mma_kernel<<<NTILES, 512, GEMM_SMEM>>>();
    row_loss_kernel<<<N, 256>>>(labels, bad, N);
    finalize_kernel<<<1, 1024>>>(out, N);
}